// round 7
// baseline (speedup 1.0000x reference)
#include <cuda_runtime.h>

// SurfEval: NURBS surface evaluation. B=8, M=N=64, P=Q=3, GRID=512, DIM=3.
//
// Two barrier-free streaming kernels (the per-block LDG->STS->BAR->LDS chain
// was the latency serializer in the fused version):
//  K1: Su[b][g][n] = sum_r Nu[g,r]*ctrl[b, us(g)-3+r, n]  -> __device__ scratch
//      (262K independent threads, MLP=4 LDG, 1 STG, no smem/sync)
//  K2: out[b,g,h] from a 5-wide Su window read directly from L2-hot scratch
//      (5 independent LDG.128 + span-shifted 5-tap weights + 3 aligned STG.128)

#define GRID_N 512
#define MCTRL 64
#define NCTRL 64
#define MAXB 8
#define SUW 65   // 64 + zero guard slot (window may touch index 64)

__device__ float4 g_Su[MAXB * GRID_N * SUW];   // 4.26 MB scratch, L2-resident

// ---------------- Kernel 1: u-contraction ----------------
// block = 256 threads = 4 rows x 64 ctrl columns. grid = B*GRID_N/4.
__global__ __launch_bounds__(256) void su_kernel(
    const float4* __restrict__ ctrl,   // (B, 64, 64) float4
    const int*    __restrict__ uspan,  // (512)
    const float4* __restrict__ Nu)     // (512) float4
{
    const int row = blockIdx.x * 4 + (threadIdx.x >> 6);   // b*512 + g
    const int n   = threadIdx.x & 63;
    const int g   = row & (GRID_N - 1);
    const int b   = row >> 9;

    const int    us = __ldg(uspan + g);
    const float4 nu = __ldg(Nu + g);

    const float4* base = ctrl + (b * MCTRL + (us - 3)) * NCTRL + n;
    const float4 c0 = __ldg(base);
    const float4 c1 = __ldg(base + NCTRL);
    const float4 c2 = __ldg(base + 2 * NCTRL);
    const float4 c3 = __ldg(base + 3 * NCTRL);

    float4 a;
    a.x = nu.x * c0.x + nu.y * c1.x + nu.z * c2.x + nu.w * c3.x;
    a.y = nu.x * c0.y + nu.y * c1.y + nu.z * c2.y + nu.w * c3.y;
    a.z = nu.x * c0.z + nu.y * c1.z + nu.z * c2.z + nu.w * c3.z;
    a.w = nu.x * c0.w + nu.y * c1.w + nu.z * c2.w + nu.w * c3.w;

    g_Su[row * SUW + n] = a;
    if (n == 0) g_Su[row * SUW + 64] = make_float4(0.f, 0.f, 0.f, 0.f);
}

// ---------------- Kernel 2: v-contraction + divide ----------------
// idx = b*65536 + g*128 + t; thread t handles h = 4t..4t+3 of row (b,g).
__global__ __launch_bounds__(256, 5) void sv_kernel(
    const int4*   __restrict__ vspan4, // (512) ints viewed as (128) int4
    const float4* __restrict__ Nv,     // (512) float4
    float4*       __restrict__ out)    // (B*512*512*3)/4 float4
{
    const int idx = blockIdx.x * 256 + threadIdx.x;
    const int t   = idx & 127;
    const int g   = (idx >> 7) & (GRID_N - 1);
    const int b   = idx >> 16;

    const int4 vsv = __ldg(vspan4 + t);
    const int  j0  = vsv.x - 3;

    // 5-wide Su window straight from L2/L1-hot scratch (independent loads).
    const float4* su = g_Su + (b * GRID_N + g) * SUW + j0;
    const float4 q0 = su[0];
    const float4 q1 = su[1];
    const float4 q2 = su[2];
    const float4 q3 = su[3];
    const float4 q4 = su[4];

    const int h0 = t << 2;
    const int vd1 = vsv.y - vsv.x, vd2 = vsv.z - vsv.x, vd3 = vsv.w - vsv.x;

    float r[12];
#pragma unroll
    for (int k = 0; k < 4; ++k) {
        const float4 nv = __ldg(Nv + h0 + k);
        const bool s = (k == 1) ? (vd1 != 0) : (k == 2) ? (vd2 != 0) : (k == 3) ? (vd3 != 0) : false;
        const float w0 = s ? 0.0f : nv.x;
        const float w1 = s ? nv.x : nv.y;
        const float w2 = s ? nv.y : nv.z;
        const float w3 = s ? nv.z : nv.w;
        const float w4 = s ? nv.w : 0.0f;

        const float X = w0 * q0.x + w1 * q1.x + w2 * q2.x + w3 * q3.x + w4 * q4.x;
        const float Y = w0 * q0.y + w1 * q1.y + w2 * q2.y + w3 * q3.y + w4 * q4.y;
        const float Z = w0 * q0.z + w1 * q1.z + w2 * q2.z + w3 * q3.z + w4 * q4.z;
        const float W = w0 * q0.w + w1 * q1.w + w2 * q2.w + w3 * q3.w + w4 * q4.w;

        const float inv = __fdividef(1.0f, W);
        r[k * 3 + 0] = X * inv;
        r[k * 3 + 1] = Y * inv;
        r[k * 3 + 2] = Z * inv;
    }

    // out row (b,g) is 384 aligned float4; thread writes float4 [3t, 3t+2].
    float4* o = out + (b * GRID_N + g) * (GRID_N * 3 / 4) + t * 3;
    o[0] = make_float4(r[0], r[1], r[2], r[3]);
    o[1] = make_float4(r[4], r[5], r[6], r[7]);
    o[2] = make_float4(r[8], r[9], r[10], r[11]);
}

extern "C" void kernel_launch(void* const* d_in, const int* in_sizes, int n_in,
                              void* d_out, int out_size) {
    const float4* ctrl   = (const float4*)d_in[0];
    const int*    uspan  = (const int*)d_in[1];
    const int4*   vspan4 = (const int4*)d_in[2];
    const float4* Nu     = (const float4*)d_in[3];
    const float4* Nv     = (const float4*)d_in[4];

    const int B = in_sizes[0] / (MCTRL * NCTRL * 4);  // ctrl_pts elements = B*64*64*4

    su_kernel<<<B * GRID_N / 4, 256>>>(ctrl, uspan, Nu);
    sv_kernel<<<B * GRID_N * 128 / 256, 256>>>(vspan4, Nv, (float4*)d_out);
}

// round 8
// speedup vs baseline: 1.1530x; 1.1530x over previous
#include <cuda_runtime.h>

// SurfEval: NURBS surface evaluation. B=8, M=N=64, P=Q=3, GRID=512, DIM=3.
//
// Key fix this round: the per-thread Nv loads (lane stride 64B -> 16 L1
// wavefronts per LDG.128, 64 wf/warp) were the dominant hidden L1 cost in all
// prior rounds. The 5-tap shifted weights + window base depend ONLY on t
// (128 values), so a tiny pre-kernel tabulates them in coalesced-friendly
// layout; the main kernel (R6 g-pair shape) reads 21 wf/warp instead of 68.

#define GRID_N 512
#define MCTRL 64
#define NCTRL 64

// Precomputed Stage-B tables (t = 0..127): 5-tap weights and window base.
__device__ float4 g_W4[4][128];   // taps 0..3 for point k of thread t
__device__ float  g_W1[4][128];   // tap 4
__device__ int    g_J[128];       // j0 = vspan[4t] - 3

// ---------------- Kernel 0: weight table (1 block, 128 threads) ----------------
__global__ void weight_kernel(const int4* __restrict__ vspan4,
                              const float4* __restrict__ Nv)
{
    const int t = threadIdx.x;
    const int4 vsv = __ldg(vspan4 + t);
    g_J[t] = vsv.x - 3;
    const int vs[4] = {vsv.x, vsv.y, vsv.z, vsv.w};
#pragma unroll
    for (int k = 0; k < 4; ++k) {
        const float4 nv = __ldg(Nv + 4 * t + k);
        const bool s = (vs[k] != vsv.x);   // span delta 0 or 1 (guaranteed)
        g_W4[k][t] = make_float4(s ? 0.0f : nv.x,
                                 s ? nv.x : nv.y,
                                 s ? nv.y : nv.z,
                                 s ? nv.z : nv.w);
        g_W1[k][t] = s ? nv.w : 0.0f;
    }
}

// ---------------- Kernel 1: fused surface eval (g-pair blocks) ----------------
__global__ __launch_bounds__(128, 9) void surf_eval_kernel(
    const float4* __restrict__ ctrl,   // (B, 64, 64) float4
    const int*    __restrict__ uspan,  // (512)
    const float4* __restrict__ Nu,     // (512) float4
    float4*       __restrict__ out)    // (B*512*512*3)/4 float4
{
    __shared__ float4 Su[2][NCTRL + 1];   // [gg][n], +1 zero guard at n=64

    const int g0 = blockIdx.x << 1;
    const int b  = blockIdx.y;
    const int t  = threadIdx.x;

    // ---- Prefetch Stage-B tables (coalesced; overlaps Stage-A latency) ----
    const int j0 = __ldg(g_J + t);
    float4 w4[4];
    float  w1[4];
#pragma unroll
    for (int k = 0; k < 4; ++k) {
        w4[k] = __ldg(&g_W4[k][t]);
        w1[k] = __ldg(&g_W1[k][t]);
    }

    // ---- Stage A: Su[gg][n] = sum_r Nu[g0+gg,r] * ctrl[b, us-3+r, n, :] ----
    {
        const int us0 = __ldg(uspan + g0);
        const int us1 = __ldg(uspan + g0 + 1);
        const int n    = t & 63;
        const int half = t >> 6;

        if (us0 == us1) {
            if (half == 0) {
                const float4 nu0 = __ldg(Nu + g0);
                const float4 nu1 = __ldg(Nu + g0 + 1);
                const float4* base = ctrl + (b * MCTRL + (us0 - 3)) * NCTRL + n;
                const float4 c0 = __ldg(base);
                const float4 c1 = __ldg(base + NCTRL);
                const float4 c2 = __ldg(base + 2 * NCTRL);
                const float4 c3 = __ldg(base + 3 * NCTRL);
                float4 a;
                a.x = nu0.x * c0.x + nu0.y * c1.x + nu0.z * c2.x + nu0.w * c3.x;
                a.y = nu0.x * c0.y + nu0.y * c1.y + nu0.z * c2.y + nu0.w * c3.y;
                a.z = nu0.x * c0.z + nu0.y * c1.z + nu0.z * c2.z + nu0.w * c3.z;
                a.w = nu0.x * c0.w + nu0.y * c1.w + nu0.z * c2.w + nu0.w * c3.w;
                Su[0][n] = a;
                a.x = nu1.x * c0.x + nu1.y * c1.x + nu1.z * c2.x + nu1.w * c3.x;
                a.y = nu1.x * c0.y + nu1.y * c1.y + nu1.z * c2.y + nu1.w * c3.y;
                a.z = nu1.x * c0.z + nu1.y * c1.z + nu1.z * c2.z + nu1.w * c3.z;
                a.w = nu1.x * c0.w + nu1.y * c1.w + nu1.z * c2.w + nu1.w * c3.w;
                Su[1][n] = a;
            }
        } else {
            const int    us = half ? us1 : us0;
            const float4 nu = __ldg(Nu + g0 + half);
            const float4* base = ctrl + (b * MCTRL + (us - 3)) * NCTRL + n;
            const float4 c0 = __ldg(base);
            const float4 c1 = __ldg(base + NCTRL);
            const float4 c2 = __ldg(base + 2 * NCTRL);
            const float4 c3 = __ldg(base + 3 * NCTRL);
            float4 a;
            a.x = nu.x * c0.x + nu.y * c1.x + nu.z * c2.x + nu.w * c3.x;
            a.y = nu.x * c0.y + nu.y * c1.y + nu.z * c2.y + nu.w * c3.y;
            a.z = nu.x * c0.z + nu.y * c1.z + nu.z * c2.z + nu.w * c3.z;
            a.w = nu.x * c0.w + nu.y * c1.w + nu.z * c2.w + nu.w * c3.w;
            Su[half][n] = a;
        }
        if (t == 124) Su[0][NCTRL] = make_float4(0.f, 0.f, 0.f, 0.f);
        if (t == 125) Su[1][NCTRL] = make_float4(0.f, 0.f, 0.f, 0.f);
    }
    __syncthreads();

    // ---- Stage B: 4 h points x 2 g-lines from precomputed weights ----
    float4* o = out + (b * GRID_N + g0) * (GRID_N * 3 / 4) + t * 3;
    const int grow = GRID_N * 3 / 4;   // float4 stride between g-lines

#pragma unroll
    for (int gg = 0; gg < 2; ++gg) {
        const float4* SuG = Su[gg];
        const float4 q0 = SuG[j0];
        const float4 q1 = SuG[j0 + 1];
        const float4 q2 = SuG[j0 + 2];
        const float4 q3 = SuG[j0 + 3];
        const float4 q4 = SuG[j0 + 4];

        float r[12];
#pragma unroll
        for (int k = 0; k < 4; ++k) {
            const float X = w4[k].x * q0.x + w4[k].y * q1.x + w4[k].z * q2.x + w4[k].w * q3.x + w1[k] * q4.x;
            const float Y = w4[k].x * q0.y + w4[k].y * q1.y + w4[k].z * q2.y + w4[k].w * q3.y + w1[k] * q4.y;
            const float Z = w4[k].x * q0.z + w4[k].y * q1.z + w4[k].z * q2.z + w4[k].w * q3.z + w1[k] * q4.z;
            const float W = w4[k].x * q0.w + w4[k].y * q1.w + w4[k].z * q2.w + w4[k].w * q3.w + w1[k] * q4.w;
            const float inv = __fdividef(1.0f, W);
            r[k * 3 + 0] = X * inv;
            r[k * 3 + 1] = Y * inv;
            r[k * 3 + 2] = Z * inv;
        }
        o[0] = make_float4(r[0], r[1], r[2], r[3]);
        o[1] = make_float4(r[4], r[5], r[6], r[7]);
        o[2] = make_float4(r[8], r[9], r[10], r[11]);
        o += grow;
    }
}

extern "C" void kernel_launch(void* const* d_in, const int* in_sizes, int n_in,
                              void* d_out, int out_size) {
    const float4* ctrl   = (const float4*)d_in[0];
    const int*    uspan  = (const int*)d_in[1];
    const int4*   vspan4 = (const int4*)d_in[2];
    const float4* Nu     = (const float4*)d_in[3];
    const float4* Nv     = (const float4*)d_in[4];

    const int B = in_sizes[0] / (MCTRL * NCTRL * 4);  // ctrl_pts elements = B*64*64*4

    weight_kernel<<<1, 128>>>(vspan4, Nv);
    dim3 grid(GRID_N / 2, B);
    surf_eval_kernel<<<grid, 128>>>(ctrl, uspan, Nu, (float4*)d_out);
}